// round 1
// baseline (speedup 1.0000x reference)
#include <cuda_runtime.h>
#include <math.h>

// ---------------------------------------------------------------------------
// MixtralMoE: T=16384 tokens, H=1024, I=3584, E=8, top-2
// Pipeline:
//   1) init        : zero counters, poison perm with -1
//   2) router      : logits -> top2 (exact fp32), per-expert counts
//   3) offsets     : exclusive scan, padded to 128-row multiples per expert
//   4) scatter     : build slot permutation + token->slot map
//   5) gemm mode 0 : g_h  = gather(x) @ w1[e]^T
//   6) gemm mode 1 : g_h  = silu(g_h) * (gather(x) @ w3[e]^T)   (fused epilogue)
//   7) gemm mode 2 : g_y  = g_h @ w2[e]^T
//   8) combine     : out[t] = w0*g_y[slot0] + w1*g_y[slot1]   (deterministic)
// ---------------------------------------------------------------------------

#define TOKENS 16384
#define HIDDEN 1024
#define INTER  3584
#define NEXP   8
#define SLOTS  (TOKENS * 2)

#define BM 128
#define BN 128
#define BK 16

#define MAXP   (SLOTS + NEXP * BM)   // 33792: worst-case padded slot count
#define MTILES (MAXP / BM)           // 264
#define ESTRIDE ((long)INTER * HIDDEN)  // per-expert weight stride (same for w1/w3/w2)

// ------------------------- device scratch (no mallocs) ---------------------
__device__ float g_h[(size_t)MAXP * INTER];   // h, then act (overwritten in-place)
__device__ float g_y[(size_t)MAXP * HIDDEN];  // down-proj result per slot
__device__ int   g_perm[MAXP];                // slot -> token (-1 = padding)
__device__ int   g_slot[SLOTS];               // (token,k) -> slot
__device__ float g_tkw[SLOTS];                // (token,k) -> renormalized weight
__device__ int   g_tke[SLOTS];                // (token,k) -> expert
__device__ int   g_cnt[NEXP];
__device__ int   g_cur[NEXP];
__device__ int   g_off[NEXP + 1];

// ------------------------------ init ---------------------------------------
__global__ void init_kernel() {
    int i = blockIdx.x * blockDim.x + threadIdx.x;
    if (i < NEXP) { g_cnt[i] = 0; g_cur[i] = 0; }
    if (i < MAXP) g_perm[i] = -1;
}

// ------------------------------ router -------------------------------------
// One warp per token. Exact fp32 logits so top-k selection matches reference.
__global__ void router_kernel(const float* __restrict__ x,
                              const float* __restrict__ gw) {
    __shared__ float sgw[NEXP * HIDDEN];  // 32 KB
    int tid = threadIdx.x;
    for (int i = tid; i < NEXP * HIDDEN; i += 256) sgw[i] = gw[i];
    __syncthreads();

    int warp = tid >> 5, lane = tid & 31;
    int t = blockIdx.x * 8 + warp;
    const float* xr = x + (long)t * HIDDEN;

    float lg[NEXP];
#pragma unroll
    for (int e = 0; e < NEXP; e++) {
        float s = 0.f;
        const float* w = sgw + e * HIDDEN;
        for (int h = lane; h < HIDDEN; h += 32) s += xr[h] * w[h];
#pragma unroll
        for (int o = 16; o > 0; o >>= 1) s += __shfl_xor_sync(0xFFFFFFFFu, s, o);
        lg[e] = s;
    }

    if (lane == 0) {
        int i0 = 0;
#pragma unroll
        for (int e = 1; e < NEXP; e++) if (lg[e] > lg[i0]) i0 = e;  // ties: lowest idx
        int i1 = -1;
#pragma unroll
        for (int e = 0; e < NEXP; e++) {
            if (e == i0) continue;
            if (i1 < 0 || lg[e] > lg[i1]) i1 = e;
        }
        // renormalized top-2 softmax weight: w0 = 1/(1+exp(l1-l0))
        float w0 = 1.f / (1.f + expf(lg[i1] - lg[i0]));
        g_tke[t * 2 + 0] = i0;  g_tkw[t * 2 + 0] = w0;
        g_tke[t * 2 + 1] = i1;  g_tkw[t * 2 + 1] = 1.f - w0;
        atomicAdd(&g_cnt[i0], 1);
        atomicAdd(&g_cnt[i1], 1);
    }
}

// ------------------------------ offsets ------------------------------------
__global__ void offsets_kernel() {
    g_off[0] = 0;
    for (int e = 0; e < NEXP; e++)
        g_off[e + 1] = g_off[e] + ((g_cnt[e] + BM - 1) / BM) * BM;
}

// ------------------------------ scatter ------------------------------------
__global__ void scatter_kernel() {
    int i = blockIdx.x * blockDim.x + threadIdx.x;
    if (i >= SLOTS) return;
    int e = g_tke[i];
    int pos = g_off[e] + atomicAdd(&g_cur[e], 1);
    g_perm[pos] = i >> 1;
    g_slot[i] = pos;
}

// ------------------------------ grouped NT GEMM ----------------------------
// C[m,n] = sum_k A[m,k] * B[n,k], B selected per expert from slot row ranges.
// mode 0: A=gather(x), B=w1 -> C=g_h (store)
// mode 1: A=gather(x), B=w3 -> C=g_h (epilogue: silu(h_old)*u)
// mode 2: A=g_h,       B=w2 -> C=g_y (store)
__global__ void __launch_bounds__(256, 2)
gemm_kernel(const float* __restrict__ x,  const float* __restrict__ w1,
            const float* __restrict__ w3, const float* __restrict__ w2,
            int mode) {
    const float* A; const float* Bb; float* C;
    int lda, ldb, ldc, Kdim;
    bool gather, act;
    if (mode == 0) { A = x;   lda = HIDDEN; Bb = w1; ldb = HIDDEN; C = g_h; ldc = INTER;  Kdim = HIDDEN; gather = true;  act = false; }
    else if (mode == 1) { A = x; lda = HIDDEN; Bb = w3; ldb = HIDDEN; C = g_h; ldc = INTER; Kdim = HIDDEN; gather = true; act = true; }
    else { A = g_h; lda = INTER;  Bb = w2; ldb = INTER;  C = g_y; ldc = HIDDEN; Kdim = INTER;  gather = false; act = false; }

    int row_base = blockIdx.y * BM;
    if (row_base >= g_off[NEXP]) return;
    int e = 0;
    while (g_off[e + 1] <= row_base) e++;
    const float* B = Bb + (long)e * ESTRIDE;
    int col_base = blockIdx.x * BN;

    __align__(16) __shared__ float As[BK][BM + 4];
    __align__(16) __shared__ float Bs[BK][BN + 4];

    int tid = threadIdx.x;
    int tr = tid >> 4;       // 0..15 -> rows tr*8..tr*8+7
    int tc = tid & 15;       // 0..15 -> cols tc*8..tc*8+7

    // Precompute global bases for the 2 float4 loads per operand per iter.
    int  arow[2]; long abase[2];
    int  brow[2]; long bbase[2];
#pragma unroll
    for (int i = 0; i < 2; i++) {
        int s  = tid + i * 256;      // 0..511
        int m  = s >> 2;             // 0..127
        int kq = (s & 3) << 2;       // 0,4,8,12
        arow[i] = m;
        int gm = row_base + m;
        int sr = gather ? g_perm[gm] : gm;
        abase[i] = (sr < 0) ? -1L : ((long)sr * lda + kq);
        brow[i] = m;
        bbase[i] = (long)(col_base + m) * ldb + kq;
    }

    float c[8][8] = {};

    for (int k0 = 0; k0 < Kdim; k0 += BK) {
#pragma unroll
        for (int i = 0; i < 2; i++) {
            int s  = tid + i * 256;
            int kq = (s & 3) << 2;
            float4 va;
            if (abase[i] < 0) va = make_float4(0.f, 0.f, 0.f, 0.f);
            else              va = *(const float4*)(A + abase[i] + k0);
            As[kq + 0][arow[i]] = va.x;
            As[kq + 1][arow[i]] = va.y;
            As[kq + 2][arow[i]] = va.z;
            As[kq + 3][arow[i]] = va.w;
            float4 vb = *(const float4*)(B + bbase[i] + k0);
            Bs[kq + 0][brow[i]] = vb.x;
            Bs[kq + 1][brow[i]] = vb.y;
            Bs[kq + 2][brow[i]] = vb.z;
            Bs[kq + 3][brow[i]] = vb.w;
        }
        __syncthreads();

#pragma unroll
        for (int k = 0; k < BK; k++) {
            float4 a0 = *(const float4*)&As[k][tr * 8];
            float4 a1 = *(const float4*)&As[k][tr * 8 + 4];
            float4 b0 = *(const float4*)&Bs[k][tc * 8];
            float4 b1 = *(const float4*)&Bs[k][tc * 8 + 4];
            float a[8] = {a0.x, a0.y, a0.z, a0.w, a1.x, a1.y, a1.z, a1.w};
            float b[8] = {b0.x, b0.y, b0.z, b0.w, b1.x, b1.y, b1.z, b1.w};
#pragma unroll
            for (int i = 0; i < 8; i++)
#pragma unroll
                for (int j = 0; j < 8; j++)
                    c[i][j] += a[i] * b[j];
        }
        __syncthreads();
    }

#pragma unroll
    for (int i = 0; i < 8; i++) {
        int m = row_base + tr * 8 + i;
        long rowoff = (long)m * ldc + col_base + tc * 8;
#pragma unroll
        for (int j = 0; j < 8; j++) {
            float v = c[i][j];
            if (act) {
                float h = C[rowoff + j];                 // h from mode-0 pass
                v *= h / (1.f + expf(-h));               // silu(h) * u
            }
            C[rowoff + j] = v;
        }
    }
}

// ------------------------------ combine ------------------------------------
__global__ void combine_kernel(float* __restrict__ out) {
    int gid = blockIdx.x * blockDim.x + threadIdx.x;   // T * H/4 threads
    int t = gid >> 8;          // H/4 = 256 float4 per row
    int c = gid & 255;
    int s0 = g_slot[t * 2 + 0], s1 = g_slot[t * 2 + 1];
    float w0 = g_tkw[t * 2 + 0], w1 = g_tkw[t * 2 + 1];
    const float4* y4 = (const float4*)g_y;
    float4 a = y4[(long)s0 * 256 + c];
    float4 b = y4[(long)s1 * 256 + c];
    float4 o;
    o.x = w0 * a.x + w1 * b.x;
    o.y = w0 * a.y + w1 * b.y;
    o.z = w0 * a.z + w1 * b.z;
    o.w = w0 * a.w + w1 * b.w;
    ((float4*)out)[gid] = o;
}

// ------------------------------ launcher -----------------------------------
extern "C" void kernel_launch(void* const* d_in, const int* in_sizes, int n_in,
                              void* d_out, int out_size) {
    const float* x  = (const float*)d_in[0];  // [T, H]
    const float* gw = (const float*)d_in[1];  // [E, H]
    const float* w1 = (const float*)d_in[2];  // [E, I, H]
    const float* w3 = (const float*)d_in[3];  // [E, I, H]
    const float* w2 = (const float*)d_in[4];  // [E, H, I]
    float* out = (float*)d_out;               // [T, H]

    init_kernel<<<(MAXP + 255) / 256, 256>>>();
    router_kernel<<<TOKENS / 8, 256>>>(x, gw);
    offsets_kernel<<<1, 1>>>();
    scatter_kernel<<<(SLOTS + 255) / 256, 256>>>();

    dim3 gUp(INTER / BN, MTILES);    // 28 x 264
    dim3 gDown(HIDDEN / BN, MTILES); // 8  x 264
    gemm_kernel<<<gUp, 256>>>(x, w1, w3, w2, 0);
    gemm_kernel<<<gUp, 256>>>(x, w1, w3, w2, 1);
    gemm_kernel<<<gDown, 256>>>(x, w1, w3, w2, 2);

    combine_kernel<<<(TOKENS * HIDDEN / 4) / 256, 256>>>(out);
}

// round 4
// speedup vs baseline: 2.6840x; 2.6840x over previous
#include <cuda_runtime.h>
#include <cstdint>
#include <math.h>

// ---------------------------------------------------------------------------
// MixtralMoE: T=16384, H=1024, I=3584, E=8, top-2.
// v4: grouped GEMMs on mma.sync.m16n8k8 tf32 (baseline PTX at compute_100).
// Fix vs v3: cvt.rna.tf32.f32 destination is .b32 -> "=r"(uint32_t), not "=f".
// Pipeline: router -> scatter -> gemm(w1) -> gemm(w3)+SwiGLU -> gemm(w2)
//           -> deterministic combine.
// ---------------------------------------------------------------------------

#define TOKENS 16384
#define HIDDEN 1024
#define INTER  3584
#define NEXP   8
#define SLOTS  (TOKENS * 2)

#define BM 128
#define BN 128
#define BK 32
#define SKF 36                     // smem row stride (floats): 32 + 4 pad
#define STAGE_F (BM * SKF)         // 4608 floats per operand per stage

#define MAXP   (SLOTS + NEXP * BM) // 33792
#define MTILES (MAXP / BM)         // 264
#define ESTRIDE ((long)INTER * HIDDEN)

#define GEMM_SMEM (4 * STAGE_F * 4)   // 2 stages x 2 operands x 4608 f = 73728 B

// ------------------------- device scratch ----------------------------------
__device__ float g_h[(size_t)MAXP * INTER];   // h, then act (in-place)
__device__ float g_y[(size_t)MAXP * HIDDEN];
__device__ int   g_perm[MAXP];
__device__ int   g_slot[SLOTS];
__device__ float g_tkw[SLOTS];
__device__ int   g_tke[SLOTS];
__device__ int   g_cnt[NEXP];
__device__ int   g_cur[NEXP];
__device__ int   g_off[NEXP + 1];

// ------------------------------ helpers -------------------------------------
// exact round-to-nearest f32 -> tf32; tf32 values live in .b32 registers
__device__ __forceinline__ uint4 cvt4(float4 v) {
    uint4 r;
    asm("cvt.rna.tf32.f32 %0, %1;" : "=r"(r.x) : "f"(v.x));
    asm("cvt.rna.tf32.f32 %0, %1;" : "=r"(r.y) : "f"(v.y));
    asm("cvt.rna.tf32.f32 %0, %1;" : "=r"(r.z) : "f"(v.z));
    asm("cvt.rna.tf32.f32 %0, %1;" : "=r"(r.w) : "f"(v.w));
    return r;
}

__device__ __forceinline__ void mma_tf32(float* c, const uint32_t* a, const uint32_t* b) {
    asm volatile(
        "mma.sync.aligned.m16n8k8.row.col.f32.tf32.tf32.f32 "
        "{%0,%1,%2,%3}, {%4,%5,%6,%7}, {%8,%9}, {%0,%1,%2,%3};"
        : "+f"(c[0]), "+f"(c[1]), "+f"(c[2]), "+f"(c[3])
        : "r"(a[0]), "r"(a[1]), "r"(a[2]), "r"(a[3]), "r"(b[0]), "r"(b[1]));
}

// ------------------------------ init ---------------------------------------
__global__ void init_kernel() {
    int i = blockIdx.x * blockDim.x + threadIdx.x;
    if (i < NEXP) { g_cnt[i] = 0; g_cur[i] = 0; }
    if (i < MAXP) g_perm[i] = -1;
}

// ------------------------------ router -------------------------------------
__global__ void router_kernel(const float* __restrict__ x,
                              const float* __restrict__ gw) {
    __shared__ float sgw[NEXP * HIDDEN];
    int tid = threadIdx.x;
    for (int i = tid; i < NEXP * HIDDEN; i += 256) sgw[i] = gw[i];
    __syncthreads();

    int warp = tid >> 5, lane = tid & 31;
    int t = blockIdx.x * 8 + warp;
    const float* xr = x + (long)t * HIDDEN;

    float lg[NEXP];
#pragma unroll
    for (int e = 0; e < NEXP; e++) {
        float s = 0.f;
        const float* w = sgw + e * HIDDEN;
        for (int h = lane; h < HIDDEN; h += 32) s += xr[h] * w[h];
#pragma unroll
        for (int o = 16; o > 0; o >>= 1) s += __shfl_xor_sync(0xFFFFFFFFu, s, o);
        lg[e] = s;
    }
    if (lane == 0) {
        int i0 = 0;
#pragma unroll
        for (int e = 1; e < NEXP; e++) if (lg[e] > lg[i0]) i0 = e;
        int i1 = -1;
#pragma unroll
        for (int e = 0; e < NEXP; e++) {
            if (e == i0) continue;
            if (i1 < 0 || lg[e] > lg[i1]) i1 = e;
        }
        float w0 = 1.f / (1.f + expf(lg[i1] - lg[i0]));
        g_tke[t * 2 + 0] = i0;  g_tkw[t * 2 + 0] = w0;
        g_tke[t * 2 + 1] = i1;  g_tkw[t * 2 + 1] = 1.f - w0;
        atomicAdd(&g_cnt[i0], 1);
        atomicAdd(&g_cnt[i1], 1);
    }
}

__global__ void offsets_kernel() {
    g_off[0] = 0;
    for (int e = 0; e < NEXP; e++)
        g_off[e + 1] = g_off[e] + ((g_cnt[e] + BM - 1) / BM) * BM;
}

__global__ void scatter_kernel() {
    int i = blockIdx.x * blockDim.x + threadIdx.x;
    if (i >= SLOTS) return;
    int e = g_tke[i];
    int pos = g_off[e] + atomicAdd(&g_cur[e], 1);
    g_perm[pos] = i >> 1;
    g_slot[i] = pos;
}

// ------------------------------ grouped NT GEMM (tensor core tf32) ---------
// C[m,n] = sum_k A[m,k] * B[n,k], expert picked by slot row range.
// mode 0: A=gather(x), B=w1 -> C=g_h           (store)
// mode 1: A=gather(x), B=w3 -> C=g_h           (epilogue: silu(h_old)*u)
// mode 2: A=g_h,       B=w2 -> C=g_y           (store)
__global__ void __launch_bounds__(256, 1)
gemm_kernel(const float* __restrict__ x,  const float* __restrict__ w1,
            const float* __restrict__ w3, const float* __restrict__ w2,
            int mode) {
    const float* A; const float* Bb; float* C;
    int lda, ldb, ldc, Kdim;
    bool gather, act;
    if (mode == 0)      { A = x;   lda = HIDDEN; Bb = w1; ldb = HIDDEN; C = g_h; ldc = INTER;  Kdim = HIDDEN; gather = true;  act = false; }
    else if (mode == 1) { A = x;   lda = HIDDEN; Bb = w3; ldb = HIDDEN; C = g_h; ldc = INTER;  Kdim = HIDDEN; gather = true;  act = true;  }
    else                { A = g_h; lda = INTER;  Bb = w2; ldb = INTER;  C = g_y; ldc = HIDDEN; Kdim = INTER;  gather = false; act = false; }

    int row_base = blockIdx.y * BM;
    if (row_base >= g_off[NEXP]) return;
    int e = 0;
    while (g_off[e + 1] <= row_base) e++;
    const float* B = Bb + (long)e * ESTRIDE;
    int col_base = blockIdx.x * BN;

    extern __shared__ float smem[];
    float* As = smem;                    // [2][STAGE_F]
    float* Bs = smem + 2 * STAGE_F;      // [2][STAGE_F]

    const int tid  = threadIdx.x;
    const int wid  = tid >> 5;
    const int lane = tid & 31;
    const int wm = wid & 3;              // warp m: 0..3 -> rows wm*32
    const int wn = wid >> 2;             // warp n: 0..1 -> cols wn*64
    const int gid = lane >> 2;           // 0..7
    const int tig = lane & 3;            // 0..3

    // ---- global prefetch mapping: 4 float4 per thread per operand ----
    long aglb[4]; int asto[4];
    long bglb[4]; int bsto[4];
#pragma unroll
    for (int j = 0; j < 4; j++) {
        int f = tid + 256 * j;           // float4 index 0..1023
        int r = f >> 3;                  // row 0..127
        int cq = (f & 7) * 4;            // col (floats) 0..28
        asto[j] = r * SKF + cq;
        bsto[j] = r * SKF + cq;
        int sr = gather ? g_perm[row_base + r] : (row_base + r);
        aglb[j] = (sr < 0) ? -1L : ((long)sr * lda + cq);
        bglb[j] = (long)(col_base + r) * ldb + cq;
    }

    const float4 z4 = make_float4(0.f, 0.f, 0.f, 0.f);
    float4 ra[4], rb[4];
#pragma unroll
    for (int j = 0; j < 4; j++) {
        ra[j] = (aglb[j] < 0) ? z4 : *(const float4*)(A + aglb[j]);
        rb[j] = *(const float4*)(B + bglb[j]);
    }

    float c[2][8][4];
#pragma unroll
    for (int t = 0; t < 2; t++)
#pragma unroll
        for (int u = 0; u < 8; u++)
#pragma unroll
            for (int v = 0; v < 4; v++) c[t][u][v] = 0.f;

    const int S = Kdim / BK;
#pragma unroll 1
    for (int s = 0; s < S; s++) {
        float* a_s = As + (s & 1) * STAGE_F;
        float* b_s = Bs + (s & 1) * STAGE_F;
        __syncthreads();   // prior readers of this buffer are done
#pragma unroll
        for (int j = 0; j < 4; j++) {
            *(uint4*)(a_s + asto[j]) = cvt4(ra[j]);
            *(uint4*)(b_s + bsto[j]) = cvt4(rb[j]);
        }
        __syncthreads();
        if (s + 1 < S) {
            int k0 = (s + 1) * BK;
#pragma unroll
            for (int j = 0; j < 4; j++) {
                ra[j] = (aglb[j] < 0) ? z4 : *(const float4*)(A + aglb[j] + k0);
                rb[j] = *(const float4*)(B + bglb[j] + k0);
            }
        }
        const uint32_t* au = (const uint32_t*)a_s;
        const uint32_t* bu = (const uint32_t*)b_s;
#pragma unroll
        for (int kk = 0; kk < BK / 8; kk++) {
            int k0 = kk * 8;
            uint32_t af[2][4];
#pragma unroll
            for (int t = 0; t < 2; t++) {
                int r = wm * 32 + t * 16 + gid;
                af[t][0] = au[r * SKF + k0 + tig];
                af[t][1] = au[(r + 8) * SKF + k0 + tig];
                af[t][2] = au[r * SKF + k0 + tig + 4];
                af[t][3] = au[(r + 8) * SKF + k0 + tig + 4];
            }
            uint32_t bf[8][2];
#pragma unroll
            for (int u = 0; u < 8; u++) {
                int n = wn * 64 + u * 8 + gid;
                bf[u][0] = bu[n * SKF + k0 + tig];
                bf[u][1] = bu[n * SKF + k0 + tig + 4];
            }
#pragma unroll
            for (int t = 0; t < 2; t++)
#pragma unroll
                for (int u = 0; u < 8; u++)
                    mma_tf32(c[t][u], af[t], bf[u]);
        }
    }

    // ---- epilogue ----
#pragma unroll
    for (int t = 0; t < 2; t++) {
        int m0 = row_base + wm * 32 + t * 16 + gid;
#pragma unroll
        for (int u = 0; u < 8; u++) {
            int n = col_base + wn * 64 + u * 8 + tig * 2;
            float* p0 = C + (long)m0 * ldc + n;
            float* p1 = C + (long)(m0 + 8) * ldc + n;
            float2 v0 = make_float2(c[t][u][0], c[t][u][1]);
            float2 v1 = make_float2(c[t][u][2], c[t][u][3]);
            if (act) {
                float2 h0 = *(const float2*)p0;
                float2 h1 = *(const float2*)p1;
                v0.x *= h0.x / (1.f + expf(-h0.x));
                v0.y *= h0.y / (1.f + expf(-h0.y));
                v1.x *= h1.x / (1.f + expf(-h1.x));
                v1.y *= h1.y / (1.f + expf(-h1.y));
            }
            *(float2*)p0 = v0;
            *(float2*)p1 = v1;
        }
    }
}

// ------------------------------ combine ------------------------------------
__global__ void combine_kernel(float* __restrict__ out) {
    int gid = blockIdx.x * blockDim.x + threadIdx.x;
    int t = gid >> 8;
    int c = gid & 255;
    int s0 = g_slot[t * 2 + 0], s1 = g_slot[t * 2 + 1];
    float w0 = g_tkw[t * 2 + 0], w1 = g_tkw[t * 2 + 1];
    const float4* y4 = (const float4*)g_y;
    float4 a = y4[(long)s0 * 256 + c];
    float4 b = y4[(long)s1 * 256 + c];
    float4 o;
    o.x = w0 * a.x + w1 * b.x;
    o.y = w0 * a.y + w1 * b.y;
    o.z = w0 * a.z + w1 * b.z;
    o.w = w0 * a.w + w1 * b.w;
    ((float4*)out)[gid] = o;
}

// ------------------------------ launcher -----------------------------------
extern "C" void kernel_launch(void* const* d_in, const int* in_sizes, int n_in,
                              void* d_out, int out_size) {
    const float* x  = (const float*)d_in[0];
    const float* gw = (const float*)d_in[1];
    const float* w1 = (const float*)d_in[2];
    const float* w3 = (const float*)d_in[3];
    const float* w2 = (const float*)d_in[4];
    float* out = (float*)d_out;

    cudaFuncSetAttribute(gemm_kernel, cudaFuncAttributeMaxDynamicSharedMemorySize, GEMM_SMEM);

    init_kernel<<<(MAXP + 255) / 256, 256>>>();
    router_kernel<<<TOKENS / 8, 256>>>(x, gw);
    offsets_kernel<<<1, 1>>>();
    scatter_kernel<<<(SLOTS + 255) / 256, 256>>>();

    dim3 gUp(INTER / BN, MTILES);    // 28 x 264
    dim3 gDn(HIDDEN / BN, MTILES);   // 8  x 264
    gemm_kernel<<<gUp, 256, GEMM_SMEM>>>(x, w1, w3, w2, 0);
    gemm_kernel<<<gUp, 256, GEMM_SMEM>>>(x, w1, w3, w2, 1);
    gemm_kernel<<<gDn, 256, GEMM_SMEM>>>(x, w1, w3, w2, 2);

    combine_kernel<<<(TOKENS * HIDDEN / 4) / 256, 256>>>(out);
}

// round 5
// speedup vs baseline: 3.1035x; 1.1563x over previous
#include <cuda_runtime.h>
#include <cuda_fp16.h>
#include <cstdint>
#include <math.h>

// ---------------------------------------------------------------------------
// MixtralMoE: T=16384, H=1024, I=3584, E=8, top-2.
// v5: fp16 m16n8k16 mma.sync (2x MAC/instr vs tf32 k8; same 10-bit mantissa),
//     fused up-kernel (w1+w3+SwiGLU, smem exchange), act stored as fp16.
// ---------------------------------------------------------------------------

#define TOKENS 16384
#define HIDDEN 1024
#define INTER  3584
#define NEXP   8
#define SLOTS  (TOKENS * 2)

#define BM 128
#define BK 32                       // K elements per stage
#define SKH 40                      // smem row stride in halves (32 + 8 pad)
#define STAGE_H (BM * SKH)          // 5120 halves = 10240 B per operand/stage

#define MAXP   (SLOTS + NEXP * BM)  // 33792
#define MTILES (MAXP / BM)          // 264
#define ESTRIDE ((long)INTER * HIDDEN)

#define K_SMEM (2 * 2 * STAGE_H * 2)  // 2 stages x 2 operands x 10240 B = 40960

// ------------------------- device scratch ----------------------------------
__device__ __half g_act[(size_t)MAXP * INTER];   // fused up output (fp16)
__device__ float  g_y[(size_t)MAXP * HIDDEN];
__device__ int    g_perm[MAXP];
__device__ int    g_slot[SLOTS];
__device__ float  g_tkw[SLOTS];
__device__ int    g_tke[SLOTS];
__device__ int    g_cnt[NEXP];
__device__ int    g_cur[NEXP];
__device__ int    g_off[NEXP + 1];

// ------------------------------ helpers -------------------------------------
__device__ __forceinline__ uint2 cvt4h(float4 v) {   // 4 x f32 -> 4 x f16 (RN)
    __half2 lo = __float22half2_rn(make_float2(v.x, v.y));
    __half2 hi = __float22half2_rn(make_float2(v.z, v.w));
    uint2 r;
    r.x = *(uint32_t*)&lo;
    r.y = *(uint32_t*)&hi;
    return r;
}

__device__ __forceinline__ void mma_f16(float* c, const uint32_t* a, const uint32_t* b) {
    asm volatile(
        "mma.sync.aligned.m16n8k16.row.col.f32.f16.f16.f32 "
        "{%0,%1,%2,%3}, {%4,%5,%6,%7}, {%8,%9}, {%0,%1,%2,%3};"
        : "+f"(c[0]), "+f"(c[1]), "+f"(c[2]), "+f"(c[3])
        : "r"(a[0]), "r"(a[1]), "r"(a[2]), "r"(a[3]), "r"(b[0]), "r"(b[1]));
}

__device__ __forceinline__ float silu(float h) { return h / (1.f + expf(-h)); }

// ------------------------------ init ---------------------------------------
__global__ void init_kernel() {
    int i = blockIdx.x * blockDim.x + threadIdx.x;
    if (i < NEXP) { g_cnt[i] = 0; g_cur[i] = 0; }
    if (i < MAXP) g_perm[i] = -1;
}

// ------------------------------ router -------------------------------------
__global__ void router_kernel(const float* __restrict__ x,
                              const float* __restrict__ gw) {
    __shared__ float sgw[NEXP * HIDDEN];
    int tid = threadIdx.x;
    for (int i = tid; i < NEXP * HIDDEN; i += 256) sgw[i] = gw[i];
    __syncthreads();

    int warp = tid >> 5, lane = tid & 31;
    int t = blockIdx.x * 8 + warp;
    const float* xr = x + (long)t * HIDDEN;

    float lg[NEXP];
#pragma unroll
    for (int e = 0; e < NEXP; e++) {
        float s = 0.f;
        const float* w = sgw + e * HIDDEN;
        for (int h = lane; h < HIDDEN; h += 32) s += xr[h] * w[h];
#pragma unroll
        for (int o = 16; o > 0; o >>= 1) s += __shfl_xor_sync(0xFFFFFFFFu, s, o);
        lg[e] = s;
    }
    if (lane == 0) {
        int i0 = 0;
#pragma unroll
        for (int e = 1; e < NEXP; e++) if (lg[e] > lg[i0]) i0 = e;
        int i1 = -1;
#pragma unroll
        for (int e = 0; e < NEXP; e++) {
            if (e == i0) continue;
            if (i1 < 0 || lg[e] > lg[i1]) i1 = e;
        }
        float w0 = 1.f / (1.f + expf(lg[i1] - lg[i0]));
        g_tke[t * 2 + 0] = i0;  g_tkw[t * 2 + 0] = w0;
        g_tke[t * 2 + 1] = i1;  g_tkw[t * 2 + 1] = 1.f - w0;
        atomicAdd(&g_cnt[i0], 1);
        atomicAdd(&g_cnt[i1], 1);
    }
}

__global__ void offsets_kernel() {
    g_off[0] = 0;
    for (int e = 0; e < NEXP; e++)
        g_off[e + 1] = g_off[e] + ((g_cnt[e] + BM - 1) / BM) * BM;
}

__global__ void scatter_kernel() {
    int i = blockIdx.x * blockDim.x + threadIdx.x;
    if (i >= SLOTS) return;
    int e = g_tke[i];
    int pos = g_off[e] + atomicAdd(&g_cur[e], 1);
    g_perm[pos] = i >> 1;
    g_slot[i] = pos;
}

// ------------------------- fused up kernel (w1 & w3 + SwiGLU) ---------------
// Block: 128 slot rows x 64 INTER cols. 8 warps: wm=wid&3 (row 32-group),
// wn=wid>>2: wn=0 computes h (w1), wn=1 computes u (w3) for the SAME cols.
// B smem rows 0..63 = w1 tile, 64..127 = w3 tile.
// Epilogue: wn=1 writes u to smem, wn=0 combines silu(h)*u -> g_act (fp16).
__global__ void __launch_bounds__(256, 1)
up_kernel(const float* __restrict__ x, const float* __restrict__ w1,
          const float* __restrict__ w3) {
    int row_base = blockIdx.y * BM;
    if (row_base >= g_off[NEXP]) return;
    int e = 0;
    while (g_off[e + 1] <= row_base) e++;
    const int col_base = blockIdx.x * 64;
    const float* __restrict__ pw1 = w1 + (long)e * ESTRIDE;
    const float* __restrict__ pw3 = w3 + (long)e * ESTRIDE;

    extern __shared__ __half smem[];
    __half* As = smem;                  // [2][STAGE_H]
    __half* Bs = smem + 2 * STAGE_H;    // [2][STAGE_H]

    const int tid  = threadIdx.x;
    const int wid  = tid >> 5;
    const int lane = tid & 31;
    const int wm = wid & 3;
    const int wn = wid >> 2;            // 0 -> w1/h, 1 -> w3/u
    const int gid = lane >> 2;
    const int tig = lane & 3;

    // A: 128 rows x 32 f32 -> 1024 float4, 4/thread. B: same (w1:64 + w3:64 rows).
    long aglb[4]; int asto[4];
    const float* bsrc[4]; int bsto[4];
#pragma unroll
    for (int j = 0; j < 4; j++) {
        int f = tid + 256 * j;
        int r = f >> 3;
        int cq = (f & 7) * 4;
        asto[j] = r * SKH + cq;
        bsto[j] = r * SKH + cq;
        int sr = g_perm[row_base + r];
        aglb[j] = (sr < 0) ? -1L : ((long)sr * HIDDEN + cq);
        bsrc[j] = (r < 64) ? (pw1 + (long)(col_base + r) * HIDDEN + cq)
                           : (pw3 + (long)(col_base + r - 64) * HIDDEN + cq);
    }

    const float4 z4 = make_float4(0.f, 0.f, 0.f, 0.f);
    uint2 ra[4], rb[4];
#pragma unroll
    for (int j = 0; j < 4; j++) {
        ra[j] = cvt4h((aglb[j] < 0) ? z4 : *(const float4*)(x + aglb[j]));
        rb[j] = cvt4h(*(const float4*)(bsrc[j]));
    }

    float c[2][8][4];
#pragma unroll
    for (int t = 0; t < 2; t++)
#pragma unroll
        for (int u = 0; u < 8; u++)
#pragma unroll
            for (int v = 0; v < 4; v++) c[t][u][v] = 0.f;

    const int S = HIDDEN / BK;  // 32
#pragma unroll 1
    for (int s = 0; s < S; s++) {
        __half* a_s = As + (s & 1) * STAGE_H;
        __half* b_s = Bs + (s & 1) * STAGE_H;
        __syncthreads();
#pragma unroll
        for (int j = 0; j < 4; j++) {
            *(uint2*)(a_s + asto[j]) = ra[j];
            *(uint2*)(b_s + bsto[j]) = rb[j];
        }
        __syncthreads();
        if (s + 1 < S) {
            int k0 = (s + 1) * BK;
#pragma unroll
            for (int j = 0; j < 4; j++) {
                ra[j] = cvt4h((aglb[j] < 0) ? z4 : *(const float4*)(x + aglb[j] + k0));
                rb[j] = cvt4h(*(const float4*)(bsrc[j] + k0));
            }
        }
        const uint32_t* au = (const uint32_t*)a_s;
        const uint32_t* bu = (const uint32_t*)b_s;
#pragma unroll
        for (int kk = 0; kk < 2; kk++) {
            int kb = kk * 8;
            uint32_t af[2][4];
#pragma unroll
            for (int t = 0; t < 2; t++) {
                int r = wm * 32 + t * 16 + gid;
                af[t][0] = au[r * (SKH / 2) + kb + tig];
                af[t][1] = au[(r + 8) * (SKH / 2) + kb + tig];
                af[t][2] = au[r * (SKH / 2) + kb + tig + 4];
                af[t][3] = au[(r + 8) * (SKH / 2) + kb + tig + 4];
            }
            uint32_t bf[8][2];
#pragma unroll
            for (int u = 0; u < 8; u++) {
                int n = wn * 64 + u * 8 + gid;
                bf[u][0] = bu[n * (SKH / 2) + kb + tig];
                bf[u][1] = bu[n * (SKH / 2) + kb + tig + 4];
            }
#pragma unroll
            for (int t = 0; t < 2; t++)
#pragma unroll
                for (int u = 0; u < 8; u++)
                    mma_f16(c[t][u], af[t], bf[u]);
        }
    }

    // ---- epilogue: exchange u through smem, combine, store fp16 act ----
    __syncthreads();
    float* ux = (float*)smem;   // 128 x 66 f32 = 33792 B <= 40960 B
    if (wn == 1) {
#pragma unroll
        for (int t = 0; t < 2; t++) {
            int r0 = wm * 32 + t * 16 + gid;
#pragma unroll
            for (int u = 0; u < 8; u++) {
                int n = u * 8 + tig * 2;
                ux[r0 * 66 + n]       = c[t][u][0];
                ux[r0 * 66 + n + 1]   = c[t][u][1];
                ux[(r0 + 8) * 66 + n]     = c[t][u][2];
                ux[(r0 + 8) * 66 + n + 1] = c[t][u][3];
            }
        }
    }
    __syncthreads();
    if (wn == 0) {
#pragma unroll
        for (int t = 0; t < 2; t++) {
            int r0 = wm * 32 + t * 16 + gid;
#pragma unroll
            for (int u = 0; u < 8; u++) {
                int n = u * 8 + tig * 2;
                float u00 = ux[r0 * 66 + n],       u01 = ux[r0 * 66 + n + 1];
                float u10 = ux[(r0 + 8) * 66 + n], u11 = ux[(r0 + 8) * 66 + n + 1];
                float a00 = silu(c[t][u][0]) * u00;
                float a01 = silu(c[t][u][1]) * u01;
                float a10 = silu(c[t][u][2]) * u10;
                float a11 = silu(c[t][u][3]) * u11;
                __half2 h0 = __float22half2_rn(make_float2(a00, a01));
                __half2 h1 = __float22half2_rn(make_float2(a10, a11));
                *(__half2*)(g_act + (size_t)(row_base + r0) * INTER + col_base + n) = h0;
                *(__half2*)(g_act + (size_t)(row_base + r0 + 8) * INTER + col_base + n) = h1;
            }
        }
    }
}

// ------------------------------ down kernel (w2) ----------------------------
// Block 128 x 128, warps 4x2, warp tile 32x64. A = g_act (fp16), B = w2 (cvt).
__global__ void __launch_bounds__(256, 1)
down_kernel(const float* __restrict__ w2) {
    int row_base = blockIdx.y * BM;
    if (row_base >= g_off[NEXP]) return;
    int e = 0;
    while (g_off[e + 1] <= row_base) e++;
    const int col_base = blockIdx.x * 128;
    const float* __restrict__ pw2 = w2 + (long)e * ESTRIDE;

    extern __shared__ __half smem[];
    __half* As = smem;
    __half* Bs = smem + 2 * STAGE_H;

    const int tid  = threadIdx.x;
    const int wid  = tid >> 5;
    const int lane = tid & 31;
    const int wm = wid & 3;
    const int wn = wid >> 2;
    const int gid = lane >> 2;
    const int tig = lane & 3;

    // A: 128 rows x 32 halves = 512 uint4, 2/thread (direct fp16 copy).
    size_t aglb[2]; int asto[2];
#pragma unroll
    for (int j = 0; j < 2; j++) {
        int f = tid + 256 * j;
        int r = f >> 2;
        int q = (f & 3) * 8;               // half offset 0,8,16,24
        asto[j] = r * SKH + q;
        aglb[j] = (size_t)(row_base + r) * INTER + q;
    }
    // B: 128 rows x 32 f32 = 1024 float4, 4/thread (cvt to fp16).
    long bglb[2]; int bsto[4];
    long bglbL[4];
#pragma unroll
    for (int j = 0; j < 4; j++) {
        int f = tid + 256 * j;
        int r = f >> 3;
        int cq = (f & 7) * 4;
        bsto[j] = r * SKH + cq;
        bglbL[j] = (long)(col_base + r) * INTER + cq;
    }
    (void)bglb;

    uint4 ra[2]; uint2 rb[4];
#pragma unroll
    for (int j = 0; j < 2; j++) ra[j] = *(const uint4*)(g_act + aglb[j]);
#pragma unroll
    for (int j = 0; j < 4; j++) rb[j] = cvt4h(*(const float4*)(pw2 + bglbL[j]));

    float c[2][8][4];
#pragma unroll
    for (int t = 0; t < 2; t++)
#pragma unroll
        for (int u = 0; u < 8; u++)
#pragma unroll
            for (int v = 0; v < 4; v++) c[t][u][v] = 0.f;

    const int S = INTER / BK;  // 112
#pragma unroll 1
    for (int s = 0; s < S; s++) {
        __half* a_s = As + (s & 1) * STAGE_H;
        __half* b_s = Bs + (s & 1) * STAGE_H;
        __syncthreads();
#pragma unroll
        for (int j = 0; j < 2; j++) *(uint4*)(a_s + asto[j]) = ra[j];
#pragma unroll
        for (int j = 0; j < 4; j++) *(uint2*)(b_s + bsto[j]) = rb[j];
        __syncthreads();
        if (s + 1 < S) {
            int k0 = (s + 1) * BK;
#pragma unroll
            for (int j = 0; j < 2; j++) ra[j] = *(const uint4*)(g_act + aglb[j] + k0);
#pragma unroll
            for (int j = 0; j < 4; j++) rb[j] = cvt4h(*(const float4*)(pw2 + bglbL[j] + k0));
        }
        const uint32_t* au = (const uint32_t*)a_s;
        const uint32_t* bu = (const uint32_t*)b_s;
#pragma unroll
        for (int kk = 0; kk < 2; kk++) {
            int kb = kk * 8;
            uint32_t af[2][4];
#pragma unroll
            for (int t = 0; t < 2; t++) {
                int r = wm * 32 + t * 16 + gid;
                af[t][0] = au[r * (SKH / 2) + kb + tig];
                af[t][1] = au[(r + 8) * (SKH / 2) + kb + tig];
                af[t][2] = au[r * (SKH / 2) + kb + tig + 4];
                af[t][3] = au[(r + 8) * (SKH / 2) + kb + tig + 4];
            }
            uint32_t bf[8][2];
#pragma unroll
            for (int u = 0; u < 8; u++) {
                int n = wn * 64 + u * 8 + gid;
                bf[u][0] = bu[n * (SKH / 2) + kb + tig];
                bf[u][1] = bu[n * (SKH / 2) + kb + tig + 4];
            }
#pragma unroll
            for (int t = 0; t < 2; t++)
#pragma unroll
                for (int u = 0; u < 8; u++)
                    mma_f16(c[t][u], af[t], bf[u]);
        }
    }

#pragma unroll
    for (int t = 0; t < 2; t++) {
        int m0 = row_base + wm * 32 + t * 16 + gid;
#pragma unroll
        for (int u = 0; u < 8; u++) {
            int n = col_base + wn * 64 + u * 8 + tig * 2;
            *(float2*)(g_y + (size_t)m0 * HIDDEN + n)       = make_float2(c[t][u][0], c[t][u][1]);
            *(float2*)(g_y + (size_t)(m0 + 8) * HIDDEN + n) = make_float2(c[t][u][2], c[t][u][3]);
        }
    }
}

// ------------------------------ combine ------------------------------------
__global__ void combine_kernel(float* __restrict__ out) {
    int gid = blockIdx.x * blockDim.x + threadIdx.x;
    int t = gid >> 8;
    int c = gid & 255;
    int s0 = g_slot[t * 2 + 0], s1 = g_slot[t * 2 + 1];
    float w0 = g_tkw[t * 2 + 0], w1 = g_tkw[t * 2 + 1];
    const float4* y4 = (const float4*)g_y;
    float4 a = y4[(long)s0 * 256 + c];
    float4 b = y4[(long)s1 * 256 + c];
    float4 o;
    o.x = w0 * a.x + w1 * b.x;
    o.y = w0 * a.y + w1 * b.y;
    o.z = w0 * a.z + w1 * b.z;
    o.w = w0 * a.w + w1 * b.w;
    ((float4*)out)[gid] = o;
}

// ------------------------------ launcher -----------------------------------
extern "C" void kernel_launch(void* const* d_in, const int* in_sizes, int n_in,
                              void* d_out, int out_size) {
    const float* x  = (const float*)d_in[0];
    const float* gw = (const float*)d_in[1];
    const float* w1 = (const float*)d_in[2];
    const float* w3 = (const float*)d_in[3];
    const float* w2 = (const float*)d_in[4];
    float* out = (float*)d_out;

    cudaFuncSetAttribute(up_kernel,   cudaFuncAttributeMaxDynamicSharedMemorySize, K_SMEM);
    cudaFuncSetAttribute(down_kernel, cudaFuncAttributeMaxDynamicSharedMemorySize, K_SMEM);

    init_kernel<<<(MAXP + 255) / 256, 256>>>();
    router_kernel<<<TOKENS / 8, 256>>>(x, gw);
    offsets_kernel<<<1, 1>>>();
    scatter_kernel<<<(SLOTS + 255) / 256, 256>>>();

    dim3 gUp(INTER / 64, MTILES);     // 56 x 264
    dim3 gDn(HIDDEN / 128, MTILES);   // 8  x 264
    up_kernel<<<gUp, 256, K_SMEM>>>(x, w1, w3);
    down_kernel<<<gDn, 256, K_SMEM>>>(w2);

    combine_kernel<<<(TOKENS * HIDDEN / 4) / 256, 256>>>(out);
}

// round 6
// speedup vs baseline: 4.7921x; 1.5441x over previous
#include <cuda_runtime.h>
#include <cuda_fp16.h>
#include <cstdint>
#include <math.h>

// ---------------------------------------------------------------------------
// MixtralMoE: T=16384, H=1024, I=3584, E=8, top-2.
// v6: v5 + occupancy 2 (reg clamp to fill sync gaps) + fp16 g_y.
// Engine: fp16 m16n8k16 mma.sync (legacy path is MAC-rate-limited ~256/cyc/SM;
// this round recovers pipeline exposure, not arithmetic).
// ---------------------------------------------------------------------------

#define TOKENS 16384
#define HIDDEN 1024
#define INTER  3584
#define NEXP   8
#define SLOTS  (TOKENS * 2)

#define BM 128
#define BK 32                       // K elements per stage
#define SKH 40                      // smem row stride in halves (32 + 8 pad)
#define STAGE_H (BM * SKH)          // 5120 halves = 10240 B per operand/stage

#define MAXP   (SLOTS + NEXP * BM)  // 33792
#define MTILES (MAXP / BM)          // 264
#define ESTRIDE ((long)INTER * HIDDEN)

#define K_SMEM (2 * 2 * STAGE_H * 2)  // 2 stages x 2 operands x 10240 B = 40960

// ------------------------- device scratch ----------------------------------
__device__ __half g_act[(size_t)MAXP * INTER];   // fused up output (fp16)
__device__ __half g_y[(size_t)MAXP * HIDDEN];    // down output (fp16)
__device__ int    g_perm[MAXP];
__device__ int    g_slot[SLOTS];
__device__ float  g_tkw[SLOTS];
__device__ int    g_tke[SLOTS];
__device__ int    g_cnt[NEXP];
__device__ int    g_cur[NEXP];
__device__ int    g_off[NEXP + 1];

// ------------------------------ helpers -------------------------------------
__device__ __forceinline__ uint2 cvt4h(float4 v) {   // 4 x f32 -> 4 x f16 (RN)
    __half2 lo = __float22half2_rn(make_float2(v.x, v.y));
    __half2 hi = __float22half2_rn(make_float2(v.z, v.w));
    uint2 r;
    r.x = *(uint32_t*)&lo;
    r.y = *(uint32_t*)&hi;
    return r;
}

__device__ __forceinline__ void mma_f16(float* c, const uint32_t* a, const uint32_t* b) {
    asm volatile(
        "mma.sync.aligned.m16n8k16.row.col.f32.f16.f16.f32 "
        "{%0,%1,%2,%3}, {%4,%5,%6,%7}, {%8,%9}, {%0,%1,%2,%3};"
        : "+f"(c[0]), "+f"(c[1]), "+f"(c[2]), "+f"(c[3])
        : "r"(a[0]), "r"(a[1]), "r"(a[2]), "r"(a[3]), "r"(b[0]), "r"(b[1]));
}

__device__ __forceinline__ float silu(float h) { return h / (1.f + expf(-h)); }

// ------------------------------ init ---------------------------------------
__global__ void init_kernel() {
    int i = blockIdx.x * blockDim.x + threadIdx.x;
    if (i < NEXP) { g_cnt[i] = 0; g_cur[i] = 0; }
    if (i < MAXP) g_perm[i] = -1;
}

// ------------------------------ router -------------------------------------
__global__ void router_kernel(const float* __restrict__ x,
                              const float* __restrict__ gw) {
    __shared__ float sgw[NEXP * HIDDEN];
    int tid = threadIdx.x;
    for (int i = tid; i < NEXP * HIDDEN; i += 256) sgw[i] = gw[i];
    __syncthreads();

    int warp = tid >> 5, lane = tid & 31;
    int t = blockIdx.x * 8 + warp;
    const float* xr = x + (long)t * HIDDEN;

    float lg[NEXP];
#pragma unroll
    for (int e = 0; e < NEXP; e++) {
        float s = 0.f;
        const float* w = sgw + e * HIDDEN;
        for (int h = lane; h < HIDDEN; h += 32) s += xr[h] * w[h];
#pragma unroll
        for (int o = 16; o > 0; o >>= 1) s += __shfl_xor_sync(0xFFFFFFFFu, s, o);
        lg[e] = s;
    }
    if (lane == 0) {
        int i0 = 0;
#pragma unroll
        for (int e = 1; e < NEXP; e++) if (lg[e] > lg[i0]) i0 = e;
        int i1 = -1;
#pragma unroll
        for (int e = 0; e < NEXP; e++) {
            if (e == i0) continue;
            if (i1 < 0 || lg[e] > lg[i1]) i1 = e;
        }
        float w0 = 1.f / (1.f + expf(lg[i1] - lg[i0]));
        g_tke[t * 2 + 0] = i0;  g_tkw[t * 2 + 0] = w0;
        g_tke[t * 2 + 1] = i1;  g_tkw[t * 2 + 1] = 1.f - w0;
        atomicAdd(&g_cnt[i0], 1);
        atomicAdd(&g_cnt[i1], 1);
    }
}

__global__ void offsets_kernel() {
    g_off[0] = 0;
    for (int e = 0; e < NEXP; e++)
        g_off[e + 1] = g_off[e] + ((g_cnt[e] + BM - 1) / BM) * BM;
}

__global__ void scatter_kernel() {
    int i = blockIdx.x * blockDim.x + threadIdx.x;
    if (i >= SLOTS) return;
    int e = g_tke[i];
    int pos = g_off[e] + atomicAdd(&g_cur[e], 1);
    g_perm[pos] = i >> 1;
    g_slot[i] = pos;
}

// ------------------------- fused up kernel (w1 & w3 + SwiGLU) ---------------
// Block: 128 slot rows x 64 INTER cols. 8 warps: wm=wid&3 (row 32-group),
// wn=wid>>2: wn=0 computes h (w1), wn=1 computes u (w3) for the SAME cols.
// B smem rows 0..63 = w1 tile, 64..127 = w3 tile.
// Epilogue: wn=1 writes u to smem, wn=0 combines silu(h)*u -> g_act (fp16).
__global__ void __launch_bounds__(256, 2)
up_kernel(const float* __restrict__ x, const float* __restrict__ w1,
          const float* __restrict__ w3) {
    int row_base = blockIdx.y * BM;
    if (row_base >= g_off[NEXP]) return;
    int e = 0;
    while (g_off[e + 1] <= row_base) e++;
    const int col_base = blockIdx.x * 64;
    const float* __restrict__ pw1 = w1 + (long)e * ESTRIDE;
    const float* __restrict__ pw3 = w3 + (long)e * ESTRIDE;

    extern __shared__ __half smem[];
    __half* As = smem;                  // [2][STAGE_H]
    __half* Bs = smem + 2 * STAGE_H;    // [2][STAGE_H]

    const int tid  = threadIdx.x;
    const int wid  = tid >> 5;
    const int lane = tid & 31;
    const int wm = wid & 3;
    const int wn = wid >> 2;            // 0 -> w1/h, 1 -> w3/u
    const int gid = lane >> 2;
    const int tig = lane & 3;

    // A: 128 rows x 32 f32 -> 1024 float4, 4/thread. B: same (w1:64 + w3:64 rows).
    long aglb[4]; int asto[4];
    const float* bsrc[4]; int bsto[4];
#pragma unroll
    for (int j = 0; j < 4; j++) {
        int f = tid + 256 * j;
        int r = f >> 3;
        int cq = (f & 7) * 4;
        asto[j] = r * SKH + cq;
        bsto[j] = r * SKH + cq;
        int sr = g_perm[row_base + r];
        aglb[j] = (sr < 0) ? -1L : ((long)sr * HIDDEN + cq);
        bsrc[j] = (r < 64) ? (pw1 + (long)(col_base + r) * HIDDEN + cq)
                           : (pw3 + (long)(col_base + r - 64) * HIDDEN + cq);
    }

    const float4 z4 = make_float4(0.f, 0.f, 0.f, 0.f);
    uint2 ra[4], rb[4];
#pragma unroll
    for (int j = 0; j < 4; j++) {
        ra[j] = cvt4h((aglb[j] < 0) ? z4 : *(const float4*)(x + aglb[j]));
        rb[j] = cvt4h(*(const float4*)(bsrc[j]));
    }

    float c[2][8][4];
#pragma unroll
    for (int t = 0; t < 2; t++)
#pragma unroll
        for (int u = 0; u < 8; u++)
#pragma unroll
            for (int v = 0; v < 4; v++) c[t][u][v] = 0.f;

    const int S = HIDDEN / BK;  // 32
#pragma unroll 1
    for (int s = 0; s < S; s++) {
        __half* a_s = As + (s & 1) * STAGE_H;
        __half* b_s = Bs + (s & 1) * STAGE_H;
        __syncthreads();
#pragma unroll
        for (int j = 0; j < 4; j++) {
            *(uint2*)(a_s + asto[j]) = ra[j];
            *(uint2*)(b_s + bsto[j]) = rb[j];
        }
        __syncthreads();
        if (s + 1 < S) {
            int k0 = (s + 1) * BK;
#pragma unroll
            for (int j = 0; j < 4; j++) {
                ra[j] = cvt4h((aglb[j] < 0) ? z4 : *(const float4*)(x + aglb[j] + k0));
                rb[j] = cvt4h(*(const float4*)(bsrc[j] + k0));
            }
        }
        const uint32_t* au = (const uint32_t*)a_s;
        const uint32_t* bu = (const uint32_t*)b_s;
#pragma unroll
        for (int kk = 0; kk < 2; kk++) {
            int kb = kk * 8;
            uint32_t af[2][4];
#pragma unroll
            for (int t = 0; t < 2; t++) {
                int r = wm * 32 + t * 16 + gid;
                af[t][0] = au[r * (SKH / 2) + kb + tig];
                af[t][1] = au[(r + 8) * (SKH / 2) + kb + tig];
                af[t][2] = au[r * (SKH / 2) + kb + tig + 4];
                af[t][3] = au[(r + 8) * (SKH / 2) + kb + tig + 4];
            }
            uint32_t bf[8][2];
#pragma unroll
            for (int u = 0; u < 8; u++) {
                int n = wn * 64 + u * 8 + gid;
                bf[u][0] = bu[n * (SKH / 2) + kb + tig];
                bf[u][1] = bu[n * (SKH / 2) + kb + tig + 4];
            }
#pragma unroll
            for (int t = 0; t < 2; t++)
#pragma unroll
                for (int u = 0; u < 8; u++)
                    mma_f16(c[t][u], af[t], bf[u]);
        }
    }

    // ---- epilogue: exchange u through smem, combine, store fp16 act ----
    __syncthreads();
    float* ux = (float*)smem;   // 128 x 66 f32 = 33792 B <= 40960 B
    if (wn == 1) {
#pragma unroll
        for (int t = 0; t < 2; t++) {
            int r0 = wm * 32 + t * 16 + gid;
#pragma unroll
            for (int u = 0; u < 8; u++) {
                int n = u * 8 + tig * 2;
                ux[r0 * 66 + n]       = c[t][u][0];
                ux[r0 * 66 + n + 1]   = c[t][u][1];
                ux[(r0 + 8) * 66 + n]     = c[t][u][2];
                ux[(r0 + 8) * 66 + n + 1] = c[t][u][3];
            }
        }
    }
    __syncthreads();
    if (wn == 0) {
#pragma unroll
        for (int t = 0; t < 2; t++) {
            int r0 = wm * 32 + t * 16 + gid;
#pragma unroll
            for (int u = 0; u < 8; u++) {
                int n = u * 8 + tig * 2;
                float u00 = ux[r0 * 66 + n],       u01 = ux[r0 * 66 + n + 1];
                float u10 = ux[(r0 + 8) * 66 + n], u11 = ux[(r0 + 8) * 66 + n + 1];
                float a00 = silu(c[t][u][0]) * u00;
                float a01 = silu(c[t][u][1]) * u01;
                float a10 = silu(c[t][u][2]) * u10;
                float a11 = silu(c[t][u][3]) * u11;
                __half2 h0 = __float22half2_rn(make_float2(a00, a01));
                __half2 h1 = __float22half2_rn(make_float2(a10, a11));
                *(__half2*)(g_act + (size_t)(row_base + r0) * INTER + col_base + n) = h0;
                *(__half2*)(g_act + (size_t)(row_base + r0 + 8) * INTER + col_base + n) = h1;
            }
        }
    }
}

// ------------------------------ down kernel (w2) ----------------------------
// Block 128 x 128, warps 4x2, warp tile 32x64. A = g_act (fp16), B = w2 (cvt).
__global__ void __launch_bounds__(256, 2)
down_kernel(const float* __restrict__ w2) {
    int row_base = blockIdx.y * BM;
    if (row_base >= g_off[NEXP]) return;
    int e = 0;
    while (g_off[e + 1] <= row_base) e++;
    const int col_base = blockIdx.x * 128;
    const float* __restrict__ pw2 = w2 + (long)e * ESTRIDE;

    extern __shared__ __half smem[];
    __half* As = smem;
    __half* Bs = smem + 2 * STAGE_H;

    const int tid  = threadIdx.x;
    const int wid  = tid >> 5;
    const int lane = tid & 31;
    const int wm = wid & 3;
    const int wn = wid >> 2;
    const int gid = lane >> 2;
    const int tig = lane & 3;

    // A: 128 rows x 32 halves = 512 uint4, 2/thread (direct fp16 copy).
    size_t aglb[2]; int asto[2];
#pragma unroll
    for (int j = 0; j < 2; j++) {
        int f = tid + 256 * j;
        int r = f >> 2;
        int q = (f & 3) * 8;               // half offset 0,8,16,24
        asto[j] = r * SKH + q;
        aglb[j] = (size_t)(row_base + r) * INTER + q;
    }
    // B: 128 rows x 32 f32 = 1024 float4, 4/thread (cvt to fp16).
    int bsto[4];
    long bglbL[4];
#pragma unroll
    for (int j = 0; j < 4; j++) {
        int f = tid + 256 * j;
        int r = f >> 3;
        int cq = (f & 7) * 4;
        bsto[j] = r * SKH + cq;
        bglbL[j] = (long)(col_base + r) * INTER + cq;
    }

    uint4 ra[2]; uint2 rb[4];
#pragma unroll
    for (int j = 0; j < 2; j++) ra[j] = *(const uint4*)(g_act + aglb[j]);
#pragma unroll
    for (int j = 0; j < 4; j++) rb[j] = cvt4h(*(const float4*)(pw2 + bglbL[j]));

    float c[2][8][4];
#pragma unroll
    for (int t = 0; t < 2; t++)
#pragma unroll
        for (int u = 0; u < 8; u++)
#pragma unroll
            for (int v = 0; v < 4; v++) c[t][u][v] = 0.f;

    const int S = INTER / BK;  // 112
#pragma unroll 1
    for (int s = 0; s < S; s++) {
        __half* a_s = As + (s & 1) * STAGE_H;
        __half* b_s = Bs + (s & 1) * STAGE_H;
        __syncthreads();
#pragma unroll
        for (int j = 0; j < 2; j++) *(uint4*)(a_s + asto[j]) = ra[j];
#pragma unroll
        for (int j = 0; j < 4; j++) *(uint2*)(b_s + bsto[j]) = rb[j];
        __syncthreads();
        if (s + 1 < S) {
            int k0 = (s + 1) * BK;
#pragma unroll
            for (int j = 0; j < 2; j++) ra[j] = *(const uint4*)(g_act + aglb[j] + k0);
#pragma unroll
            for (int j = 0; j < 4; j++) rb[j] = cvt4h(*(const float4*)(pw2 + bglbL[j] + k0));
        }
        const uint32_t* au = (const uint32_t*)a_s;
        const uint32_t* bu = (const uint32_t*)b_s;
#pragma unroll
        for (int kk = 0; kk < 2; kk++) {
            int kb = kk * 8;
            uint32_t af[2][4];
#pragma unroll
            for (int t = 0; t < 2; t++) {
                int r = wm * 32 + t * 16 + gid;
                af[t][0] = au[r * (SKH / 2) + kb + tig];
                af[t][1] = au[(r + 8) * (SKH / 2) + kb + tig];
                af[t][2] = au[r * (SKH / 2) + kb + tig + 4];
                af[t][3] = au[(r + 8) * (SKH / 2) + kb + tig + 4];
            }
            uint32_t bf[8][2];
#pragma unroll
            for (int u = 0; u < 8; u++) {
                int n = wn * 64 + u * 8 + gid;
                bf[u][0] = bu[n * (SKH / 2) + kb + tig];
                bf[u][1] = bu[n * (SKH / 2) + kb + tig + 4];
            }
#pragma unroll
            for (int t = 0; t < 2; t++)
#pragma unroll
                for (int u = 0; u < 8; u++)
                    mma_f16(c[t][u], af[t], bf[u]);
        }
    }

#pragma unroll
    for (int t = 0; t < 2; t++) {
        int m0 = row_base + wm * 32 + t * 16 + gid;
#pragma unroll
        for (int u = 0; u < 8; u++) {
            int n = col_base + wn * 64 + u * 8 + tig * 2;
            __half2 y0 = __float22half2_rn(make_float2(c[t][u][0], c[t][u][1]));
            __half2 y1 = __float22half2_rn(make_float2(c[t][u][2], c[t][u][3]));
            *(__half2*)(g_y + (size_t)m0 * HIDDEN + n)       = y0;
            *(__half2*)(g_y + (size_t)(m0 + 8) * HIDDEN + n) = y1;
        }
    }
}

// ------------------------------ combine ------------------------------------
__global__ void combine_kernel(float* __restrict__ out) {
    int gid = blockIdx.x * blockDim.x + threadIdx.x;   // T*H/4 threads
    int t = gid >> 8;
    int c = gid & 255;                                 // float4 col
    int s0 = g_slot[t * 2 + 0], s1 = g_slot[t * 2 + 1];
    float w0 = g_tkw[t * 2 + 0], w1 = g_tkw[t * 2 + 1];
    const uint2* ya = (const uint2*)(g_y + (size_t)s0 * HIDDEN) + c;
    const uint2* yb = (const uint2*)(g_y + (size_t)s1 * HIDDEN) + c;
    uint2 pa = *ya, pb = *yb;
    float2 a0 = __half22float2(*(__half2*)&pa.x);
    float2 a1 = __half22float2(*(__half2*)&pa.y);
    float2 b0 = __half22float2(*(__half2*)&pb.x);
    float2 b1 = __half22float2(*(__half2*)&pb.y);
    float4 o;
    o.x = w0 * a0.x + w1 * b0.x;
    o.y = w0 * a0.y + w1 * b0.y;
    o.z = w0 * a1.x + w1 * b1.x;
    o.w = w0 * a1.y + w1 * b1.y;
    ((float4*)out)[gid] = o;
}

// ------------------------------ launcher -----------------------------------
extern "C" void kernel_launch(void* const* d_in, const int* in_sizes, int n_in,
                              void* d_out, int out_size) {
    const float* x  = (const float*)d_in[0];
    const float* gw = (const float*)d_in[1];
    const float* w1 = (const float*)d_in[2];
    const float* w3 = (const float*)d_in[3];
    const float* w2 = (const float*)d_in[4];
    float* out = (float*)d_out;

    cudaFuncSetAttribute(up_kernel,   cudaFuncAttributeMaxDynamicSharedMemorySize, K_SMEM);
    cudaFuncSetAttribute(down_kernel, cudaFuncAttributeMaxDynamicSharedMemorySize, K_SMEM);

    init_kernel<<<(MAXP + 255) / 256, 256>>>();
    router_kernel<<<TOKENS / 8, 256>>>(x, gw);
    offsets_kernel<<<1, 1>>>();
    scatter_kernel<<<(SLOTS + 255) / 256, 256>>>();

    dim3 gUp(INTER / 64, MTILES);     // 56 x 264
    dim3 gDn(HIDDEN / 128, MTILES);   // 8  x 264
    up_kernel<<<gUp, 256, K_SMEM>>>(x, w1, w3);
    down_kernel<<<gDn, 256, K_SMEM>>>(w2);

    combine_kernel<<<(TOKENS * HIDDEN / 4) / 256, 256>>>(out);
}

// round 7
// speedup vs baseline: 6.5211x; 1.3608x over previous
#include <cuda_runtime.h>
#include <cuda_fp16.h>
#include <cstdint>
#include <math.h>

// ---------------------------------------------------------------------------
// MixtralMoE: T=16384, H=1024, I=3584, E=8, top-2.
// v7: pre-converted fp16 operands + cp.async 4-stage pipeline + ldmatrix
//     fragment loads. Engine: mma.sync.m16n8k16.f16 (f32 accum).
// ---------------------------------------------------------------------------

#define TOKENS 16384
#define HIDDEN 1024
#define INTER  3584
#define NEXP   8
#define SLOTS  (TOKENS * 2)

#define BM 128
#define BK 32                        // K halves per stage
#define SKH 40                       // smem row stride in halves (80 B)
#define STAGE_B (BM * SKH * 2)       // 10240 B per operand per stage
#define NST 4
#define K_SMEM (NST * 2 * STAGE_B)   // 81920 B

#define MAXP   (SLOTS + NEXP * BM)   // 33792
#define MTILES (MAXP / BM)           // 264
#define ESTRIDE ((long)INTER * HIDDEN)

// ------------------------- device scratch ----------------------------------
__device__ __half g_xh[(size_t)TOKENS * HIDDEN];
__device__ __half g_w1h[(size_t)NEXP * ESTRIDE];
__device__ __half g_w3h[(size_t)NEXP * ESTRIDE];
__device__ __half g_w2h[(size_t)NEXP * ESTRIDE];
__device__ __half g_act[(size_t)MAXP * INTER];
__device__ __half g_y[(size_t)MAXP * HIDDEN];
__device__ int    g_perm[MAXP];
__device__ int    g_slot[SLOTS];
__device__ float  g_tkw[SLOTS];
__device__ int    g_tke[SLOTS];
__device__ int    g_cnt[NEXP];
__device__ int    g_cur[NEXP];
__device__ int    g_off[NEXP + 1];

// ------------------------------ helpers -------------------------------------
__device__ __forceinline__ uint32_t smem_u32(const void* p) {
    return (uint32_t)__cvta_generic_to_shared(p);
}

#define CP_ASYNC16(dst_u32, src_ptr, szr) \
    asm volatile("cp.async.cg.shared.global [%0], [%1], 16, %2;" \
        :: "r"(dst_u32), "l"(src_ptr), "r"(szr))
#define CP_COMMIT() asm volatile("cp.async.commit_group;" ::: "memory")
#define CP_WAIT2()  asm volatile("cp.async.wait_group 2;" ::: "memory")

#define LDSM_X4(r0, r1, r2, r3, a) \
    asm volatile("ldmatrix.sync.aligned.m8n8.x4.shared.b16 {%0,%1,%2,%3}, [%4];" \
        : "=r"(r0), "=r"(r1), "=r"(r2), "=r"(r3) : "r"(a))

__device__ __forceinline__ void mma_f16(float* c, const uint32_t* a, const uint32_t* b) {
    asm volatile(
        "mma.sync.aligned.m16n8k16.row.col.f32.f16.f16.f32 "
        "{%0,%1,%2,%3}, {%4,%5,%6,%7}, {%8,%9}, {%0,%1,%2,%3};"
        : "+f"(c[0]), "+f"(c[1]), "+f"(c[2]), "+f"(c[3])
        : "r"(a[0]), "r"(a[1]), "r"(a[2]), "r"(a[3]), "r"(b[0]), "r"(b[1]));
}

__device__ __forceinline__ float silu(float h) { return h / (1.f + expf(-h)); }

// ------------------------------ cvt f32 -> f16 ------------------------------
__global__ void cvt_kernel(const float* __restrict__ src, __half* __restrict__ dst,
                           int n4) {
    int i = blockIdx.x * blockDim.x + threadIdx.x;
    if (i >= n4) return;
    float4 v = ((const float4*)src)[i];
    __half2 lo = __float22half2_rn(make_float2(v.x, v.y));
    __half2 hi = __float22half2_rn(make_float2(v.z, v.w));
    uint2 p;
    p.x = *(uint32_t*)&lo;
    p.y = *(uint32_t*)&hi;
    ((uint2*)dst)[i] = p;
}

// ------------------------------ init ---------------------------------------
__global__ void init_kernel() {
    int i = blockIdx.x * blockDim.x + threadIdx.x;
    if (i < NEXP) { g_cnt[i] = 0; g_cur[i] = 0; }
    if (i < MAXP) g_perm[i] = -1;
}

// ------------------------------ router -------------------------------------
__global__ void router_kernel(const float* __restrict__ x,
                              const float* __restrict__ gw) {
    __shared__ float sgw[NEXP * HIDDEN];
    int tid = threadIdx.x;
    for (int i = tid; i < NEXP * HIDDEN; i += 256) sgw[i] = gw[i];
    __syncthreads();

    int warp = tid >> 5, lane = tid & 31;
    int t = blockIdx.x * 8 + warp;
    const float* xr = x + (long)t * HIDDEN;

    float lg[NEXP];
#pragma unroll
    for (int e = 0; e < NEXP; e++) {
        float s = 0.f;
        const float* w = sgw + e * HIDDEN;
        for (int h = lane; h < HIDDEN; h += 32) s += xr[h] * w[h];
#pragma unroll
        for (int o = 16; o > 0; o >>= 1) s += __shfl_xor_sync(0xFFFFFFFFu, s, o);
        lg[e] = s;
    }
    if (lane == 0) {
        int i0 = 0;
#pragma unroll
        for (int e = 1; e < NEXP; e++) if (lg[e] > lg[i0]) i0 = e;
        int i1 = -1;
#pragma unroll
        for (int e = 0; e < NEXP; e++) {
            if (e == i0) continue;
            if (i1 < 0 || lg[e] > lg[i1]) i1 = e;
        }
        float w0 = 1.f / (1.f + expf(lg[i1] - lg[i0]));
        g_tke[t * 2 + 0] = i0;  g_tkw[t * 2 + 0] = w0;
        g_tke[t * 2 + 1] = i1;  g_tkw[t * 2 + 1] = 1.f - w0;
        atomicAdd(&g_cnt[i0], 1);
        atomicAdd(&g_cnt[i1], 1);
    }
}

__global__ void offsets_kernel() {
    g_off[0] = 0;
    for (int e = 0; e < NEXP; e++)
        g_off[e + 1] = g_off[e] + ((g_cnt[e] + BM - 1) / BM) * BM;
}

__global__ void scatter_kernel() {
    int i = blockIdx.x * blockDim.x + threadIdx.x;
    if (i >= SLOTS) return;
    int e = g_tke[i];
    int pos = g_off[e] + atomicAdd(&g_cur[e], 1);
    g_perm[pos] = i >> 1;
    g_slot[i] = pos;
}

// ---------------------------------------------------------------------------
// Fragment compute (shared by both GEMM kernels):
// warp tile 32(m) x 64(n), fragments via ldmatrix, BK=32 per stage (2 k16).
// ---------------------------------------------------------------------------
__device__ __forceinline__ void stage_mma(uint32_t a_u32, uint32_t b_u32,
                                          int wm, int wn, int lane,
                                          float c[2][8][4]) {
    const int mat = lane >> 3, r = lane & 7;
#pragma unroll
    for (int kk = 0; kk < 2; kk++) {
        uint32_t af[2][4];
#pragma unroll
        for (int t = 0; t < 2; t++) {
            int row = wm * 32 + t * 16 + ((mat & 1) << 3) + r;
            int kc  = kk * 16 + ((mat >> 1) << 3);
            LDSM_X4(af[t][0], af[t][1], af[t][2], af[t][3],
                    a_u32 + (uint32_t)(row * (SKH * 2) + kc * 2));
        }
        uint32_t bf[8][2];
#pragma unroll
        for (int ug = 0; ug < 4; ug++) {
            int u = ug * 2;
            int n  = wn * 64 + (u + (mat >> 1)) * 8 + r;
            int kc = kk * 16 + ((mat & 1) << 3);
            LDSM_X4(bf[u][0], bf[u][1], bf[u + 1][0], bf[u + 1][1],
                    b_u32 + (uint32_t)(n * (SKH * 2) + kc * 2));
        }
#pragma unroll
        for (int t = 0; t < 2; t++)
#pragma unroll
            for (int u = 0; u < 8; u++)
                mma_f16(c[t][u], af[t], bf[u]);
    }
}

// ------------------------- fused up kernel (w1 & w3 + SwiGLU) ---------------
// Block: 128 slot rows x 64 INTER cols. wn=0 -> h (w1), wn=1 -> u (w3).
// B smem rows 0..63 = w1 tile, 64..127 = w3 tile.
__global__ void __launch_bounds__(256, 2)
up_kernel() {
    int row_base = blockIdx.y * BM;
    if (row_base >= g_off[NEXP]) return;
    int e = 0;
    while (g_off[e + 1] <= row_base) e++;
    const int col_base = blockIdx.x * 64;
    const __half* __restrict__ pw1 = g_w1h + (size_t)e * ESTRIDE;
    const __half* __restrict__ pw3 = g_w3h + (size_t)e * ESTRIDE;

    extern __shared__ __half smem[];
    const uint32_t sb = smem_u32(smem);

    const int tid  = threadIdx.x;
    const int wid  = tid >> 5;
    const int lane = tid & 31;
    const int wm = wid & 3;
    const int wn = wid >> 2;

    // cp.async chunks: A 512 16B-chunks, B 512 -> 2 each per thread.
    const __half* asrc[2]; uint32_t adst[2]; uint32_t asz[2];
    const __half* bsrc[2]; uint32_t bdst[2];
#pragma unroll
    for (int j = 0; j < 2; j++) {
        int cch = tid + 256 * j;
        int r = cch >> 2, q = cch & 3;
        adst[j] = (uint32_t)(r * 80 + q * 16);
        bdst[j] = (uint32_t)(r * 80 + q * 16);
        int sr = g_perm[row_base + r];
        asrc[j] = g_xh + ((sr < 0) ? 0 : (size_t)sr * HIDDEN) + q * 8;
        asz[j]  = (sr < 0) ? 0u : 16u;
        bsrc[j] = (r < 64) ? (pw1 + (size_t)(col_base + r) * HIDDEN + q * 8)
                           : (pw3 + (size_t)(col_base + r - 64) * HIDDEN + q * 8);
    }

    float c[2][8][4];
#pragma unroll
    for (int t = 0; t < 2; t++)
#pragma unroll
        for (int u = 0; u < 8; u++)
#pragma unroll
            for (int v = 0; v < 4; v++) c[t][u][v] = 0.f;

    const int S = HIDDEN / BK;  // 32
    // prologue: stages 0..NST-2
#pragma unroll
    for (int s = 0; s < NST - 1; s++) {
        uint32_t base = sb + s * (2 * STAGE_B);
#pragma unroll
        for (int j = 0; j < 2; j++) {
            CP_ASYNC16(base + adst[j], asrc[j] + s * BK, asz[j]);
            CP_ASYNC16(base + STAGE_B + bdst[j], bsrc[j] + s * BK, 16u);
        }
        CP_COMMIT();
    }

#pragma unroll 1
    for (int s = 0; s < S; s++) {
        CP_WAIT2();
        __syncthreads();
        int sn = s + NST - 1;
        if (sn < S) {
            uint32_t base = sb + (sn % NST) * (2 * STAGE_B);
#pragma unroll
            for (int j = 0; j < 2; j++) {
                CP_ASYNC16(base + adst[j], asrc[j] + sn * BK, asz[j]);
                CP_ASYNC16(base + STAGE_B + bdst[j], bsrc[j] + sn * BK, 16u);
            }
        }
        CP_COMMIT();
        uint32_t base = sb + (s % NST) * (2 * STAGE_B);
        stage_mma(base, base + STAGE_B, wm, wn, lane, c);
    }

    // ---- epilogue: exchange u through smem, combine, store fp16 act ----
    __syncthreads();
    float* ux = (float*)smem;   // 128 x 66 f32 = 33792 B <= 81920
    const int gid = lane >> 2, tig = lane & 3;
    if (wn == 1) {
#pragma unroll
        for (int t = 0; t < 2; t++) {
            int r0 = wm * 32 + t * 16 + gid;
#pragma unroll
            for (int u = 0; u < 8; u++) {
                int n = u * 8 + tig * 2;
                ux[r0 * 66 + n]           = c[t][u][0];
                ux[r0 * 66 + n + 1]       = c[t][u][1];
                ux[(r0 + 8) * 66 + n]     = c[t][u][2];
                ux[(r0 + 8) * 66 + n + 1] = c[t][u][3];
            }
        }
    }
    __syncthreads();
    if (wn == 0) {
#pragma unroll
        for (int t = 0; t < 2; t++) {
            int r0 = wm * 32 + t * 16 + gid;
#pragma unroll
            for (int u = 0; u < 8; u++) {
                int n = u * 8 + tig * 2;
                float u00 = ux[r0 * 66 + n],       u01 = ux[r0 * 66 + n + 1];
                float u10 = ux[(r0 + 8) * 66 + n], u11 = ux[(r0 + 8) * 66 + n + 1];
                __half2 h0 = __float22half2_rn(make_float2(silu(c[t][u][0]) * u00,
                                                           silu(c[t][u][1]) * u01));
                __half2 h1 = __float22half2_rn(make_float2(silu(c[t][u][2]) * u10,
                                                           silu(c[t][u][3]) * u11));
                *(__half2*)(g_act + (size_t)(row_base + r0) * INTER + col_base + n) = h0;
                *(__half2*)(g_act + (size_t)(row_base + r0 + 8) * INTER + col_base + n) = h1;
            }
        }
    }
}

// ------------------------------ down kernel (w2) ----------------------------
// Block 128 x 128, warps 4x2, warp tile 32x64. A = g_act, B = g_w2h.
__global__ void __launch_bounds__(256, 2)
down_kernel() {
    int row_base = blockIdx.y * BM;
    if (row_base >= g_off[NEXP]) return;
    int e = 0;
    while (g_off[e + 1] <= row_base) e++;
    const int col_base = blockIdx.x * 128;
    const __half* __restrict__ pw2 = g_w2h + (size_t)e * ESTRIDE;

    extern __shared__ __half smem[];
    const uint32_t sb = smem_u32(smem);

    const int tid  = threadIdx.x;
    const int wid  = tid >> 5;
    const int lane = tid & 31;
    const int wm = wid & 3;
    const int wn = wid >> 2;

    const __half* asrc[2]; uint32_t adst[2];
    const __half* bsrc[2]; uint32_t bdst[2];
#pragma unroll
    for (int j = 0; j < 2; j++) {
        int cch = tid + 256 * j;
        int r = cch >> 2, q = cch & 3;
        adst[j] = (uint32_t)(r * 80 + q * 16);
        bdst[j] = (uint32_t)(r * 80 + q * 16);
        asrc[j] = g_act + (size_t)(row_base + r) * INTER + q * 8;
        bsrc[j] = pw2 + (size_t)(col_base + r) * INTER + q * 8;
    }

    float c[2][8][4];
#pragma unroll
    for (int t = 0; t < 2; t++)
#pragma unroll
        for (int u = 0; u < 8; u++)
#pragma unroll
            for (int v = 0; v < 4; v++) c[t][u][v] = 0.f;

    const int S = INTER / BK;  // 112
#pragma unroll
    for (int s = 0; s < NST - 1; s++) {
        uint32_t base = sb + s * (2 * STAGE_B);
#pragma unroll
        for (int j = 0; j < 2; j++) {
            CP_ASYNC16(base + adst[j], asrc[j] + s * BK, 16u);
            CP_ASYNC16(base + STAGE_B + bdst[j], bsrc[j] + s * BK, 16u);
        }
        CP_COMMIT();
    }

#pragma unroll 1
    for (int s = 0; s < S; s++) {
        CP_WAIT2();
        __syncthreads();
        int sn = s + NST - 1;
        if (sn < S) {
            uint32_t base = sb + (sn % NST) * (2 * STAGE_B);
#pragma unroll
            for (int j = 0; j < 2; j++) {
                CP_ASYNC16(base + adst[j], asrc[j] + sn * BK, 16u);
                CP_ASYNC16(base + STAGE_B + bdst[j], bsrc[j] + sn * BK, 16u);
            }
        }
        CP_COMMIT();
        uint32_t base = sb + (s % NST) * (2 * STAGE_B);
        stage_mma(base, base + STAGE_B, wm, wn, lane, c);
    }

    const int gid = lane >> 2, tig = lane & 3;
#pragma unroll
    for (int t = 0; t < 2; t++) {
        int m0 = row_base + wm * 32 + t * 16 + gid;
#pragma unroll
        for (int u = 0; u < 8; u++) {
            int n = col_base + wn * 64 + u * 8 + tig * 2;
            __half2 y0 = __float22half2_rn(make_float2(c[t][u][0], c[t][u][1]));
            __half2 y1 = __float22half2_rn(make_float2(c[t][u][2], c[t][u][3]));
            *(__half2*)(g_y + (size_t)m0 * HIDDEN + n)       = y0;
            *(__half2*)(g_y + (size_t)(m0 + 8) * HIDDEN + n) = y1;
        }
    }
}

// ------------------------------ combine ------------------------------------
__global__ void combine_kernel(float* __restrict__ out) {
    int gid = blockIdx.x * blockDim.x + threadIdx.x;
    int t = gid >> 8;
    int c = gid & 255;
    int s0 = g_slot[t * 2 + 0], s1 = g_slot[t * 2 + 1];
    float w0 = g_tkw[t * 2 + 0], w1 = g_tkw[t * 2 + 1];
    uint2 pa = *((const uint2*)(g_y + (size_t)s0 * HIDDEN) + c);
    uint2 pb = *((const uint2*)(g_y + (size_t)s1 * HIDDEN) + c);
    float2 a0 = __half22float2(*(__half2*)&pa.x);
    float2 a1 = __half22float2(*(__half2*)&pa.y);
    float2 b0 = __half22float2(*(__half2*)&pb.x);
    float2 b1 = __half22float2(*(__half2*)&pb.y);
    float4 o;
    o.x = w0 * a0.x + w1 * b0.x;
    o.y = w0 * a0.y + w1 * b0.y;
    o.z = w0 * a1.x + w1 * b1.x;
    o.w = w0 * a1.y + w1 * b1.y;
    ((float4*)out)[gid] = o;
}

// ------------------------------ launcher -----------------------------------
extern "C" void kernel_launch(void* const* d_in, const int* in_sizes, int n_in,
                              void* d_out, int out_size) {
    const float* x  = (const float*)d_in[0];
    const float* gw = (const float*)d_in[1];
    const float* w1 = (const float*)d_in[2];
    const float* w3 = (const float*)d_in[3];
    const float* w2 = (const float*)d_in[4];
    float* out = (float*)d_out;

    cudaFuncSetAttribute(up_kernel,   cudaFuncAttributeMaxDynamicSharedMemorySize, K_SMEM);
    cudaFuncSetAttribute(down_kernel, cudaFuncAttributeMaxDynamicSharedMemorySize, K_SMEM);

    // resolve device scratch pointers for cvt targets
    __half *xh, *w1h, *w3h, *w2h;
    cudaGetSymbolAddress((void**)&xh,  g_xh);
    cudaGetSymbolAddress((void**)&w1h, g_w1h);
    cudaGetSymbolAddress((void**)&w3h, g_w3h);
    cudaGetSymbolAddress((void**)&w2h, g_w2h);

    init_kernel<<<(MAXP + 255) / 256, 256>>>();
    router_kernel<<<TOKENS / 8, 256>>>(x, gw);

    const int W4 = NEXP * INTER * HIDDEN / 4;   // 7340032
    const int X4 = TOKENS * HIDDEN / 4;         // 4194304
    cvt_kernel<<<(X4 + 255) / 256, 256>>>(x,  xh,  X4);
    cvt_kernel<<<(W4 + 255) / 256, 256>>>(w1, w1h, W4);
    cvt_kernel<<<(W4 + 255) / 256, 256>>>(w3, w3h, W4);
    cvt_kernel<<<(W4 + 255) / 256, 256>>>(w2, w2h, W4);

    offsets_kernel<<<1, 1>>>();
    scatter_kernel<<<(SLOTS + 255) / 256, 256>>>();

    dim3 gUp(INTER / 64, MTILES);     // 56 x 264
    dim3 gDn(HIDDEN / 128, MTILES);   // 8  x 264
    up_kernel<<<gUp, 256, K_SMEM>>>();
    down_kernel<<<gDn, 256, K_SMEM>>>();

    combine_kernel<<<(TOKENS * HIDDEN / 4) / 256, 256>>>(out);
}